// round 14
// baseline (speedup 1.0000x reference)
#include <cuda_runtime.h>
#include <cuda_bf16.h>
#include <cuda_fp8.h>
#include <cstdint>

static constexpr int ROW = 1024;   // H * D = 8 * 128 elements per slot row

// index width flag: 1 if index arrays are int64, 0 if int32 (probe-classified; proven in R12)
__device__ int g_idx64;

__global__ void probe_idx_kernel(const uint32_t* __restrict__ blocks_w) {
    if (threadIdx.x != 0 || blockIdx.x != 0) return;
    // int64 values < 2^32 have zero high (odd) 32-bit words; int32 random indices don't
    int odd_zeros = 0;
    for (int i = 0; i < 256; i++) {
        if (blocks_w[2 * i + 1] == 0u) odd_zeros++;
    }
    g_idx64 = (odd_zeros > 200) ? 1 : 0;
}

__device__ __forceinline__ int load_index(const void* p, int i, int idx64) {
    if (idx64) return (int)reinterpret_cast<const long long*>(p)[i];
    return reinterpret_cast<const int*>(p)[i];
}

// f32 -> fp8 e4m3 (rn, satfinite) -> f32, exact round-trip quantization
__device__ __forceinline__ float2 quant_fp8(float2 f) {
    const __nv_fp8x2_storage_t p = __nv_cvt_float2_to_fp8x2(f, __NV_SATFINITE, __NV_E4M3);
    __half2_raw h = __nv_cvt_fp8x2_to_halfraw2(p, __NV_E4M3);
    return __half22float2(*reinterpret_cast<__half2*>(&h));
}

// -------- kernel 1: quantize f32 input -> fp8 values (stored as f32), scatter into cache rows --------
// one thread = 8 elems (two float4 loads/stores); 128 threads per token row
__global__ void __launch_bounds__(256)
scatter_quant_kernel(const float* __restrict__ inp,
                     float* __restrict__ cache,
                     const void* __restrict__ slots,
                     int total_chunks) {
    const int idx = blockIdx.x * blockDim.x + threadIdx.x;
    if (idx >= total_chunks) return;
    const int token = idx >> 7;      // 128 chunks per token
    const int chunk = idx & 127;

    const float4* src = reinterpret_cast<const float4*>(inp) + ((size_t)token * 128 + chunk) * 2;
    const float4 a = src[0];
    const float4 b = src[1];

    const float2 d0 = quant_fp8(make_float2(a.x, a.y));
    const float2 d1 = quant_fp8(make_float2(a.z, a.w));
    const float2 d2 = quant_fp8(make_float2(b.x, b.y));
    const float2 d3 = quant_fp8(make_float2(b.z, b.w));

    const int slot = load_index(slots, token, g_idx64);   // uniform within 128-thread group
    float4* base = reinterpret_cast<float4*>(cache + (size_t)slot * ROW + (size_t)chunk * 8);
    base[0] = make_float4(d0.x, d0.y, d1.x, d1.y);
    base[1] = make_float4(d2.x, d2.y, d3.x, d3.y);
}

// -------- kernel 2: gather f32 cache rows -> f32 output (pure row copy, scales = 1.0) --------
// one thread = 16 elems = 64 B; 64 threads per fetched row of 4 KB
__global__ void __launch_bounds__(256)
gather_kernel(const float* __restrict__ cache,
              const void* __restrict__ blocks,
              float* __restrict__ out,
              int total_chunks /* num_fetch * 64 */) {
    const int idx = blockIdx.x * blockDim.x + threadIdx.x;
    if (idx >= total_chunks) return;
    const int row = idx >> 6;        // 64 chunks of 16 f32 per fetched row
    const int col = idx & 63;

    const int slot = load_index(blocks, row, g_idx64);    // uniform within 64-thread group
    const float4* src = reinterpret_cast<const float4*>(cache + (size_t)slot * ROW) + 4 * col;
    float4* dst = reinterpret_cast<float4*>(out + (size_t)row * ROW) + 4 * col;

    const float4 a = src[0];
    const float4 b = src[1];
    const float4 c = src[2];
    const float4 d = src[3];
    dst[0] = a;
    dst[1] = b;
    dst[2] = c;
    dst[3] = d;
}

extern "C" void kernel_launch(void* const* d_in, const int* in_sizes, int n_in,
                              void* d_out, int out_size) {
    // Bind inputs by element count (pairwise distinct):
    //   cache = 268435456 (f32), input = 8388608 (f32), blocks = 32768, slot_mapping = 8192
    int idx_sorted[8];
    for (int i = 0; i < n_in; i++) idx_sorted[i] = i;
    for (int i = 0; i < n_in; i++)
        for (int j = i + 1; j < n_in; j++)
            if ((long long)in_sizes[idx_sorted[j]] > (long long)in_sizes[idx_sorted[i]]) {
                int t = idx_sorted[i]; idx_sorted[i] = idx_sorted[j]; idx_sorted[j] = t;
            }

    float* cache             = (float*)d_in[idx_sorted[0]];
    const float* inp         = (const float*)d_in[idx_sorted[1]];
    const void* blocks       = d_in[idx_sorted[2]];
    const void* slot_mapping = d_in[idx_sorted[3]];
    float* out               = (float*)d_out;

    const int num_tokens = in_sizes[idx_sorted[1]] / ROW;   // 8192
    const int num_fetch  = out_size / ROW;                  // 32768

    // 0) probe index width (tiny, capture-safe, deterministic)
    probe_idx_kernel<<<1, 32>>>((const uint32_t*)blocks);

    // 1) scatter+quant: num_tokens * 128 chunks of 8 elems
    {
        const int total = num_tokens * (ROW / 8);
        const int threads = 256;
        const int grid = (total + threads - 1) / threads;
        scatter_quant_kernel<<<grid, threads>>>(inp, cache, slot_mapping, total);
    }
    // 2) gather (stream-ordered after scatter): num_fetch * 64 chunks of 16 f32
    {
        const int total = num_fetch * (ROW / 16);
        const int threads = 256;
        const int grid = (total + threads - 1) / threads;
        gather_kernel<<<grid, threads>>>(cache, blocks, out, total);
    }
}